// round 1
// baseline (speedup 1.0000x reference)
#include <cuda_runtime.h>
#include <cuda_bf16.h>
#include <math.h>
#include <stdint.h>

// Problem constants
#define T_TOK   2048          // B*S tokens
#define D_HID   2048          // hidden
#define N_INT   1024          // intermediate
#define N_EXP   8
#define N_SLOT  (T_TOK * 2)   // top-2 => 4096 (token,k) slots, always all used

// ---------------------------------------------------------------------------
// Scratch (static device globals; no allocation in kernel_launch)
// ---------------------------------------------------------------------------
__device__ float g_h[(size_t)N_SLOT * N_INT];        // 16 MB: h per slot (expert-grouped order)
__device__ float g_oslots[(size_t)N_SLOT * D_HID];   // 32 MB: down-proj per (token,k), token-indexed
__device__ int   g_counts[N_EXP];
__device__ int   g_offsets[N_EXP];
__device__ int   g_cursor[N_EXP];
__device__ int   g_tk_e[N_SLOT];                     // expert idx per (token,k)
__device__ float g_tk_w[N_SLOT];                     // routing weight per (token,k)
__device__ int   g_slot_tok2[N_SLOT];                // slot -> token*2+k   (expert-grouped)
__device__ float g_slot_w[N_SLOT];                   // slot -> routing weight

// ---------------------------------------------------------------------------
// Helpers
// ---------------------------------------------------------------------------
__device__ __forceinline__ float to_tf32(float f) {
    // Round-to-nearest tf32 (unbiased). Truncation would bias results ~-1e-3.
    uint32_t u;
    asm("cvt.rna.tf32.f32 %0, %1;" : "=r"(u) : "f"(f));
    return __uint_as_float(u);
}

__device__ __forceinline__ float gelu_exact(float v) {
    return 0.5f * v * (1.0f + erff(v * 0.70710678118654752f));
}

__device__ __forceinline__ void mma_tf32(float c[4], const uint32_t a[4], const uint32_t b[2]) {
    asm volatile(
        "mma.sync.aligned.m16n8k8.row.col.f32.tf32.tf32.f32 "
        "{%0,%1,%2,%3}, {%4,%5,%6,%7}, {%8,%9}, {%0,%1,%2,%3};"
        : "+f"(c[0]), "+f"(c[1]), "+f"(c[2]), "+f"(c[3])
        : "r"(a[0]), "r"(a[1]), "r"(a[2]), "r"(a[3]), "r"(b[0]), "r"(b[1]));
}

// ---------------------------------------------------------------------------
// 1) init: zero per-expert counts (graph replays require re-init each launch)
// ---------------------------------------------------------------------------
__global__ void init_kernel() {
    if (threadIdx.x < N_EXP) g_counts[threadIdx.x] = 0;
}

// ---------------------------------------------------------------------------
// 2) router: logits, top-2, softmax weights, per-expert counts
//    one block per token, 8 warps = 8 experts
// ---------------------------------------------------------------------------
__global__ void router_kernel(const float* __restrict__ x,
                              const float* __restrict__ gw,
                              const float* __restrict__ gb,
                              float* __restrict__ logits_out) {
    int t    = blockIdx.x;
    int warp = threadIdx.x >> 5;
    int lane = threadIdx.x & 31;
    const float* xr = x + (size_t)t * D_HID;

    float s = 0.0f;
    for (int i = lane; i < D_HID; i += 32)
        s += xr[i] * gw[i * N_EXP + warp];
#pragma unroll
    for (int o = 16; o; o >>= 1)
        s += __shfl_xor_sync(0xffffffffu, s, o);

    __shared__ float lg[N_EXP];
    if (lane == 0) lg[warp] = s + gb[warp];
    __syncthreads();

    if (threadIdx.x == 0) {
        float v0 = -1e30f, v1 = -1e30f;
        int e0 = 0, e1 = 0;
#pragma unroll
        for (int e = 0; e < N_EXP; e++) {
            float v = lg[e];
            logits_out[(size_t)t * N_EXP + e] = v;
            if (v > v0)      { v1 = v0; e1 = e0; v0 = v; e0 = e; }
            else if (v > v1) { v1 = v;  e1 = e; }
        }
        float d  = expf(v1 - v0);           // v1 <= v0, stable softmax over 2
        float w1 = d / (1.0f + d);
        float w0 = 1.0f - w1;
        g_tk_e[2 * t]     = e0;  g_tk_w[2 * t]     = w0;
        g_tk_e[2 * t + 1] = e1;  g_tk_w[2 * t + 1] = w1;
        atomicAdd(&g_counts[e0], 1);
        atomicAdd(&g_counts[e1], 1);
    }
}

// ---------------------------------------------------------------------------
// 3) offsets: serial exclusive scan over 8 experts
// ---------------------------------------------------------------------------
__global__ void offsets_kernel() {
    if (threadIdx.x == 0) {
        int run = 0;
        for (int e = 0; e < N_EXP; e++) {
            g_offsets[e] = run;
            g_cursor[e]  = run;
            run += g_counts[e];
        }
    }
}

// ---------------------------------------------------------------------------
// 4) scatter: (token,k) -> expert-grouped slot list
//    (slot order within an expert is nondeterministic, but each slot's OUTPUT
//     depends only on (token,k,expert,weight) => results are deterministic)
// ---------------------------------------------------------------------------
__global__ void scatter_kernel() {
    int i = blockIdx.x * blockDim.x + threadIdx.x;
    if (i < N_SLOT) {
        int e   = g_tk_e[i];
        int pos = atomicAdd(&g_cursor[e], 1);
        g_slot_tok2[pos] = i;
        g_slot_w[pos]    = g_tk_w[i];
    }
}

// ---------------------------------------------------------------------------
// GEMM tiles: 64x64 per block (128 thr = 4 warps, warp tile 32x32), BK=32
// tf32 m16n8k8. Smem pads: A stride 36 (banks 4g+q), B stride 72 (banks 8q+g)
// ---------------------------------------------------------------------------
#define BM 64
#define BN 64
#define BK 32

// 5) fused up+gate GEMM per expert: h = gelu(x@Wu) * (x@Wg + 1)
__global__ void __launch_bounds__(128)
gemm1_kernel(const float* __restrict__ x,
             const float* __restrict__ w_up,
             const float* __restrict__ w_gate) {
    int e   = blockIdx.z;
    int cnt = g_counts[e];
    int m0  = blockIdx.y * BM;
    if (m0 >= cnt) return;
    int n0  = blockIdx.x * BN;
    int off = g_offsets[e];

    const float* Wu = w_up   + (size_t)e * D_HID * N_INT;
    const float* Wg = w_gate + (size_t)e * D_HID * N_INT;

    __shared__ float As[BM][36];
    __shared__ float BuS[BK][72];
    __shared__ float BgS[BK][72];

    int tid  = threadIdx.x;
    int warp = tid >> 5, lane = tid & 31;
    int grp  = lane >> 2, qid = lane & 3;
    int wm   = warp >> 1, wn  = warp & 1;

    // Per-thread gathered A row pointers (fixed across K loop)
    const float* aptr[4];
    int arow = tid >> 3;
    int ac4  = tid & 7;
#pragma unroll
    for (int i = 0; i < 4; i++) {
        int r  = arow + 16 * i;
        int gm = m0 + r;
        if (gm < cnt) {
            int tok = g_slot_tok2[off + gm] >> 1;
            aptr[i] = x + (size_t)tok * D_HID + ac4 * 4;
        } else {
            aptr[i] = nullptr;  // zero-fill (masked in epilogue anyway)
        }
    }
    int bkr = tid >> 4;
    int bc4 = tid & 15;

    float accU[2][4][4], accG[2][4][4];
#pragma unroll
    for (int a = 0; a < 2; a++)
#pragma unroll
        for (int b = 0; b < 4; b++)
#pragma unroll
            for (int c = 0; c < 4; c++) { accU[a][b][c] = 0.f; accG[a][b][c] = 0.f; }

    for (int k0 = 0; k0 < D_HID; k0 += BK) {
        // A: 64x32 gathered rows
#pragma unroll
        for (int i = 0; i < 4; i++) {
            float4 v = make_float4(0.f, 0.f, 0.f, 0.f);
            if (aptr[i]) v = *(const float4*)(aptr[i] + k0);
            float* dst = &As[arow + 16 * i][ac4 * 4];
            dst[0] = to_tf32(v.x); dst[1] = to_tf32(v.y);
            dst[2] = to_tf32(v.z); dst[3] = to_tf32(v.w);
        }
        // B: 32x64 for both matrices
#pragma unroll
        for (int i = 0; i < 4; i++) {
            int kr = bkr + 8 * i;
            size_t go = (size_t)(k0 + kr) * N_INT + n0 + bc4 * 4;
            float4 u = *(const float4*)(Wu + go);
            float4 g = *(const float4*)(Wg + go);
            float* du = &BuS[kr][bc4 * 4];
            du[0] = to_tf32(u.x); du[1] = to_tf32(u.y); du[2] = to_tf32(u.z); du[3] = to_tf32(u.w);
            float* dg = &BgS[kr][bc4 * 4];
            dg[0] = to_tf32(g.x); dg[1] = to_tf32(g.y); dg[2] = to_tf32(g.z); dg[3] = to_tf32(g.w);
        }
        __syncthreads();

#pragma unroll
        for (int ks = 0; ks < 4; ks++) {
            int kk = ks * 8;
            uint32_t a[2][4];
#pragma unroll
            for (int fm = 0; fm < 2; fm++) {
                int rb = wm * 32 + fm * 16;
                a[fm][0] = __float_as_uint(As[rb + grp][kk + qid]);
                a[fm][1] = __float_as_uint(As[rb + grp + 8][kk + qid]);
                a[fm][2] = __float_as_uint(As[rb + grp][kk + qid + 4]);
                a[fm][3] = __float_as_uint(As[rb + grp + 8][kk + qid + 4]);
            }
            uint32_t bu[4][2], bg[4][2];
#pragma unroll
            for (int fn = 0; fn < 4; fn++) {
                int cb = wn * 32 + fn * 8 + grp;
                bu[fn][0] = __float_as_uint(BuS[kk + qid][cb]);
                bu[fn][1] = __float_as_uint(BuS[kk + qid + 4][cb]);
                bg[fn][0] = __float_as_uint(BgS[kk + qid][cb]);
                bg[fn][1] = __float_as_uint(BgS[kk + qid + 4][cb]);
            }
#pragma unroll
            for (int fm = 0; fm < 2; fm++)
#pragma unroll
                for (int fn = 0; fn < 4; fn++) {
                    mma_tf32(accU[fm][fn], a[fm], bu[fn]);
                    mma_tf32(accG[fm][fn], a[fm], bg[fn]);
                }
        }
        __syncthreads();
    }

    // Epilogue: h = gelu(up) * (gate + 1) -> g_h[slot][n]
#pragma unroll
    for (int fm = 0; fm < 2; fm++) {
        int r0 = wm * 32 + fm * 16 + grp;
#pragma unroll
        for (int half = 0; half < 2; half++) {
            int gm = m0 + r0 + half * 8;
            if (gm < cnt) {
                int slot = off + gm;
                float* hrow = g_h + (size_t)slot * N_INT + n0;
#pragma unroll
                for (int fn = 0; fn < 4; fn++) {
                    int c = wn * 32 + fn * 8 + qid * 2;
                    float u0 = accU[fm][fn][half * 2 + 0];
                    float u1 = accU[fm][fn][half * 2 + 1];
                    float g0 = accG[fm][fn][half * 2 + 0];
                    float g1 = accG[fm][fn][half * 2 + 1];
                    hrow[c]     = gelu_exact(u0) * (g0 + 1.0f);
                    hrow[c + 1] = gelu_exact(u1) * (g1 + 1.0f);
                }
            }
        }
    }
}

// 6) down GEMM per expert: out_slot = w_route * (h @ Wd)
__global__ void __launch_bounds__(128)
gemm2_kernel(const float* __restrict__ w_down) {
    int e   = blockIdx.z;
    int cnt = g_counts[e];
    int m0  = blockIdx.y * BM;
    if (m0 >= cnt) return;
    int n0  = blockIdx.x * BN;
    int off = g_offsets[e];

    const float* Wd = w_down + (size_t)e * N_INT * D_HID;

    __shared__ float As[BM][36];
    __shared__ float BdS[BK][72];

    int tid  = threadIdx.x;
    int warp = tid >> 5, lane = tid & 31;
    int grp  = lane >> 2, qid = lane & 3;
    int wm   = warp >> 1, wn  = warp & 1;

    int arow = tid >> 3;
    int ac4  = tid & 7;
    const float* aptr[4];
#pragma unroll
    for (int i = 0; i < 4; i++) {
        int r    = arow + 16 * i;
        int gm   = m0 + r;
        int slot = (gm < cnt) ? (off + gm) : 0;  // clamp; masked in epilogue
        aptr[i]  = g_h + (size_t)slot * N_INT + ac4 * 4;
    }
    int bkr = tid >> 4;
    int bc4 = tid & 15;

    float acc[2][4][4];
#pragma unroll
    for (int a = 0; a < 2; a++)
#pragma unroll
        for (int b = 0; b < 4; b++)
#pragma unroll
            for (int c = 0; c < 4; c++) acc[a][b][c] = 0.f;

    for (int k0 = 0; k0 < N_INT; k0 += BK) {
#pragma unroll
        for (int i = 0; i < 4; i++) {
            float4 v = *(const float4*)(aptr[i] + k0);
            float* dst = &As[arow + 16 * i][ac4 * 4];
            dst[0] = to_tf32(v.x); dst[1] = to_tf32(v.y);
            dst[2] = to_tf32(v.z); dst[3] = to_tf32(v.w);
        }
#pragma unroll
        for (int i = 0; i < 4; i++) {
            int kr = bkr + 8 * i;
            float4 u = *(const float4*)(Wd + (size_t)(k0 + kr) * D_HID + n0 + bc4 * 4);
            float* dd = &BdS[kr][bc4 * 4];
            dd[0] = to_tf32(u.x); dd[1] = to_tf32(u.y); dd[2] = to_tf32(u.z); dd[3] = to_tf32(u.w);
        }
        __syncthreads();

#pragma unroll
        for (int ks = 0; ks < 4; ks++) {
            int kk = ks * 8;
            uint32_t a[2][4];
#pragma unroll
            for (int fm = 0; fm < 2; fm++) {
                int rb = wm * 32 + fm * 16;
                a[fm][0] = __float_as_uint(As[rb + grp][kk + qid]);
                a[fm][1] = __float_as_uint(As[rb + grp + 8][kk + qid]);
                a[fm][2] = __float_as_uint(As[rb + grp][kk + qid + 4]);
                a[fm][3] = __float_as_uint(As[rb + grp + 8][kk + qid + 4]);
            }
            uint32_t bd[4][2];
#pragma unroll
            for (int fn = 0; fn < 4; fn++) {
                int cb = wn * 32 + fn * 8 + grp;
                bd[fn][0] = __float_as_uint(BdS[kk + qid][cb]);
                bd[fn][1] = __float_as_uint(BdS[kk + qid + 4][cb]);
            }
#pragma unroll
            for (int fm = 0; fm < 2; fm++)
#pragma unroll
                for (int fn = 0; fn < 4; fn++)
                    mma_tf32(acc[fm][fn], a[fm], bd[fn]);
        }
        __syncthreads();
    }

    // Epilogue: scale by routing weight, write to slot buffer row (token*2+k)
#pragma unroll
    for (int fm = 0; fm < 2; fm++) {
        int r0 = wm * 32 + fm * 16 + grp;
#pragma unroll
        for (int half = 0; half < 2; half++) {
            int gm = m0 + r0 + half * 8;
            if (gm < cnt) {
                int slot  = off + gm;
                int dest  = g_slot_tok2[slot];
                float wv  = g_slot_w[slot];
                float* orow = g_oslots + (size_t)dest * D_HID + n0;
#pragma unroll
                for (int fn = 0; fn < 4; fn++) {
                    int c = wn * 32 + fn * 8 + qid * 2;
                    orow[c]     = wv * acc[fm][fn][half * 2 + 0];
                    orow[c + 1] = wv * acc[fm][fn][half * 2 + 1];
                }
            }
        }
    }
}

// ---------------------------------------------------------------------------
// 7) combine: out[t] = oslots[2t] + oslots[2t+1]  (deterministic, no atomics)
// ---------------------------------------------------------------------------
__global__ void combine_kernel(float* __restrict__ out) {
    int i = blockIdx.x * blockDim.x + threadIdx.x;   // float4 index over T*D/4
    int t = i >> 9;                                  // 512 float4 per row
    int c = (i & 511) << 2;
    const float4 a = *(const float4*)(g_oslots + ((size_t)(2 * t)) * D_HID + c);
    const float4 b = *(const float4*)(g_oslots + ((size_t)(2 * t) + 1) * D_HID + c);
    float4 r;
    r.x = a.x + b.x; r.y = a.y + b.y; r.z = a.z + b.z; r.w = a.w + b.w;
    *(float4*)(out + (size_t)t * D_HID + c) = r;
}

// ---------------------------------------------------------------------------
// Launch
// ---------------------------------------------------------------------------
extern "C" void kernel_launch(void* const* d_in, const int* in_sizes, int n_in,
                              void* d_out, int out_size) {
    const float* x  = (const float*)d_in[0];   // [2,1024,2048]
    const float* gw = (const float*)d_in[1];   // [2048,8]
    const float* gb = (const float*)d_in[2];   // [8]
    const float* wu = (const float*)d_in[3];   // [8,2048,1024]
    const float* wg = (const float*)d_in[4];   // [8,2048,1024]
    const float* wd = (const float*)d_in[5];   // [8,1024,2048]

    float* out    = (float*)d_out;                         // out first
    float* logits = out + (out_size - T_TOK * N_EXP);      // router logits last

    init_kernel<<<1, 32>>>();
    router_kernel<<<T_TOK, 256>>>(x, gw, gb, logits);
    offsets_kernel<<<1, 32>>>();
    scatter_kernel<<<(N_SLOT + 255) / 256, 256>>>();

    dim3 g1(N_INT / BN, N_SLOT / BM, N_EXP);   // (16, 64, 8)
    gemm1_kernel<<<g1, 128>>>(x, wu, wg);

    dim3 g2(D_HID / BN, N_SLOT / BM, N_EXP);   // (32, 64, 8)
    gemm2_kernel<<<g2, 128>>>(wd);

    combine_kernel<<<(T_TOK * D_HID / 4) / 256, 256>>>(out);
}

// round 2
// speedup vs baseline: 1.0442x; 1.0442x over previous
#include <cuda_runtime.h>
#include <cuda_bf16.h>
#include <math.h>
#include <stdint.h>

// Problem constants
#define T_TOK   2048
#define D_HID   2048
#define N_INT   1024
#define N_EXP   8
#define N_SLOT  (T_TOK * 2)

// ---------------------------------------------------------------------------
// Scratch
// ---------------------------------------------------------------------------
__device__ float g_h[(size_t)N_SLOT * N_INT];
__device__ float g_oslots[(size_t)N_SLOT * D_HID];
__device__ int   g_counts[N_EXP];
__device__ int   g_offsets[N_EXP];
__device__ int   g_cursor[N_EXP];
__device__ int   g_tk_e[N_SLOT];
__device__ float g_tk_w[N_SLOT];
__device__ int   g_slot_tok2[N_SLOT];
__device__ float g_slot_w[N_SLOT];

// ---------------------------------------------------------------------------
// Helpers
// ---------------------------------------------------------------------------
__device__ __forceinline__ uint32_t f2tf32(float f) {
    uint32_t u;
    asm("cvt.rna.tf32.f32 %0, %1;" : "=r"(u) : "f"(f));
    return u;
}
__device__ __forceinline__ float gelu_exact(float v) {
    return 0.5f * v * (1.0f + erff(v * 0.70710678118654752f));
}
__device__ __forceinline__ void mma_tf32(float c[4], const uint32_t a[4], const uint32_t b[2]) {
    asm volatile(
        "mma.sync.aligned.m16n8k8.row.col.f32.tf32.tf32.f32 "
        "{%0,%1,%2,%3}, {%4,%5,%6,%7}, {%8,%9}, {%0,%1,%2,%3};"
        : "+f"(c[0]), "+f"(c[1]), "+f"(c[2]), "+f"(c[3])
        : "r"(a[0]), "r"(a[1]), "r"(a[2]), "r"(a[3]), "r"(b[0]), "r"(b[1]));
}
__device__ __forceinline__ void cp_async16(void* smem_dst, const void* gmem_src) {
    uint32_t s = (uint32_t)__cvta_generic_to_shared(smem_dst);
    asm volatile("cp.async.cg.shared.global [%0], [%1], 16;\n" :: "r"(s), "l"(gmem_src));
}
__device__ __forceinline__ void cp_commit() { asm volatile("cp.async.commit_group;\n" ::: "memory"); }
template<int N>
__device__ __forceinline__ void cp_wait() { asm volatile("cp.async.wait_group %0;\n" :: "n"(N) : "memory"); }

// ---------------------------------------------------------------------------
// 1) init
// ---------------------------------------------------------------------------
__global__ void init_kernel() {
    if (threadIdx.x < N_EXP) g_counts[threadIdx.x] = 0;
}

// ---------------------------------------------------------------------------
// 2) router
// ---------------------------------------------------------------------------
__global__ void router_kernel(const float* __restrict__ x,
                              const float* __restrict__ gw,
                              const float* __restrict__ gb,
                              float* __restrict__ logits_out) {
    int t    = blockIdx.x;
    int warp = threadIdx.x >> 5;
    int lane = threadIdx.x & 31;
    const float* xr = x + (size_t)t * D_HID;

    float s = 0.0f;
    for (int i = lane; i < D_HID; i += 32)
        s += xr[i] * gw[i * N_EXP + warp];
#pragma unroll
    for (int o = 16; o; o >>= 1)
        s += __shfl_xor_sync(0xffffffffu, s, o);

    __shared__ float lg[N_EXP];
    if (lane == 0) lg[warp] = s + gb[warp];
    __syncthreads();

    if (threadIdx.x == 0) {
        float v0 = -1e30f, v1 = -1e30f;
        int e0 = 0, e1 = 0;
#pragma unroll
        for (int e = 0; e < N_EXP; e++) {
            float v = lg[e];
            logits_out[(size_t)t * N_EXP + e] = v;
            if (v > v0)      { v1 = v0; e1 = e0; v0 = v; e0 = e; }
            else if (v > v1) { v1 = v;  e1 = e; }
        }
        float d  = expf(v1 - v0);
        float w1 = d / (1.0f + d);
        float w0 = 1.0f - w1;
        g_tk_e[2 * t]     = e0;  g_tk_w[2 * t]     = w0;
        g_tk_e[2 * t + 1] = e1;  g_tk_w[2 * t + 1] = w1;
        atomicAdd(&g_counts[e0], 1);
        atomicAdd(&g_counts[e1], 1);
    }
}

// ---------------------------------------------------------------------------
// 3) offsets
// ---------------------------------------------------------------------------
__global__ void offsets_kernel() {
    if (threadIdx.x == 0) {
        int run = 0;
        for (int e = 0; e < N_EXP; e++) {
            g_offsets[e] = run;
            g_cursor[e]  = run;
            run += g_counts[e];
        }
    }
}

// ---------------------------------------------------------------------------
// 4) scatter
// ---------------------------------------------------------------------------
__global__ void scatter_kernel() {
    int i = blockIdx.x * blockDim.x + threadIdx.x;
    if (i < N_SLOT) {
        int e   = g_tk_e[i];
        int pos = atomicAdd(&g_cursor[e], 1);
        g_slot_tok2[pos] = i;
        g_slot_w[pos]    = g_tk_w[i];
    }
}

// ---------------------------------------------------------------------------
// GEMM 1: h = gelu(x@Wu) * (x@Wg + 1), tiles 128x64x32, 256 thr, 3-stage
//   smem per stage: A 128x36, Bu 32x72, Bg 32x72  (floats)
// ---------------------------------------------------------------------------
#define G1_BM 128
#define G1_BN 64
#define G1_BK 32
#define G1_AS 36     // A row stride (floats)
#define G1_BS 72     // B row stride (floats)
#define G1_A_SZ   (G1_BM * G1_AS)          // 4608
#define G1_B_SZ   (G1_BK * G1_BS)          // 2304
#define G1_STAGE  (G1_A_SZ + 2 * G1_B_SZ)  // 9216 floats
#define STAGES 3

extern __shared__ float smem_dyn[];

__global__ void __launch_bounds__(256)
gemm1_kernel(const float* __restrict__ x,
             const float* __restrict__ w_up,
             const float* __restrict__ w_gate) {
    int e   = blockIdx.z;
    int cnt = g_counts[e];
    int m0  = blockIdx.y * G1_BM;
    if (m0 >= cnt) return;
    int n0  = blockIdx.x * G1_BN;
    int off = g_offsets[e];

    const float* Wu = w_up   + (size_t)e * D_HID * N_INT;
    const float* Wg = w_gate + (size_t)e * D_HID * N_INT;

    float* As = smem_dyn;                         // [STAGES][128][36]
    float* Bu = smem_dyn + STAGES * G1_A_SZ;      // [STAGES][32][72]
    float* Bg = Bu + STAGES * G1_B_SZ;            // [STAGES][32][72]

    int tid  = threadIdx.x;
    int warp = tid >> 5, lane = tid & 31;
    int grp  = lane >> 2, qid = lane & 3;
    int wm   = warp >> 1, wn  = warp & 1;         // 4x2 warp grid, 32x32 tiles

    // A gather pointers (4 rows per thread)
    int arow = tid >> 3;          // 0..31
    int acol = (tid & 7) * 4;     // float col
    const float* aptr[4];
#pragma unroll
    for (int i = 0; i < 4; i++) {
        int gm   = m0 + arow + 32 * i;
        int slot = (gm < cnt) ? (off + gm) : off;   // clamp to valid memory
        int tok  = g_slot_tok2[slot] >> 1;
        aptr[i]  = x + (size_t)tok * D_HID + acol;
    }
    int brow = tid >> 4;          // 0..15
    int bcol = (tid & 15) * 4;

    float accU[2][4][4], accG[2][4][4];
#pragma unroll
    for (int a = 0; a < 2; a++)
#pragma unroll
        for (int b = 0; b < 4; b++)
#pragma unroll
            for (int c = 0; c < 4; c++) { accU[a][b][c] = 0.f; accG[a][b][c] = 0.f; }

    const int KT = D_HID / G1_BK;   // 64

    auto load_stage = [&](int s, int k0) {
        float* a = As + s * G1_A_SZ;
#pragma unroll
        for (int i = 0; i < 4; i++)
            cp_async16(a + (arow + 32 * i) * G1_AS + acol, aptr[i] + k0);
        float* bu = Bu + s * G1_B_SZ;
        float* bg = Bg + s * G1_B_SZ;
#pragma unroll
        for (int i = 0; i < 2; i++) {
            int kr = brow + 16 * i;
            size_t go = (size_t)(k0 + kr) * N_INT + n0 + bcol;
            cp_async16(bu + kr * G1_BS + bcol, Wu + go);
            cp_async16(bg + kr * G1_BS + bcol, Wg + go);
        }
        cp_commit();
    };

#pragma unroll
    for (int s = 0; s < STAGES - 1; s++) load_stage(s, s * G1_BK);

    for (int kt = 0; kt < KT; kt++) {
        cp_wait<STAGES - 2>();
        __syncthreads();

        int nkt = kt + STAGES - 1;
        if (nkt < KT) load_stage(nkt % STAGES, nkt * G1_BK);
        else          cp_commit();

        int s = kt % STAGES;
        const float* a  = As + s * G1_A_SZ;
        const float* bu = Bu + s * G1_B_SZ;
        const float* bg = Bg + s * G1_B_SZ;

#pragma unroll
        for (int ks = 0; ks < 4; ks++) {
            int kk = ks * 8;
            uint32_t af[2][4];
#pragma unroll
            for (int fm = 0; fm < 2; fm++) {
                int rb = wm * 32 + fm * 16;
                af[fm][0] = f2tf32(a[(rb + grp)     * G1_AS + kk + qid]);
                af[fm][1] = f2tf32(a[(rb + grp + 8) * G1_AS + kk + qid]);
                af[fm][2] = f2tf32(a[(rb + grp)     * G1_AS + kk + qid + 4]);
                af[fm][3] = f2tf32(a[(rb + grp + 8) * G1_AS + kk + qid + 4]);
            }
            uint32_t bfu[4][2], bfg[4][2];
#pragma unroll
            for (int fn = 0; fn < 4; fn++) {
                int cb = wn * 32 + fn * 8 + grp;
                bfu[fn][0] = f2tf32(bu[(kk + qid)     * G1_BS + cb]);
                bfu[fn][1] = f2tf32(bu[(kk + qid + 4) * G1_BS + cb]);
                bfg[fn][0] = f2tf32(bg[(kk + qid)     * G1_BS + cb]);
                bfg[fn][1] = f2tf32(bg[(kk + qid + 4) * G1_BS + cb]);
            }
#pragma unroll
            for (int fm = 0; fm < 2; fm++)
#pragma unroll
                for (int fn = 0; fn < 4; fn++) {
                    mma_tf32(accU[fm][fn], af[fm], bfu[fn]);
                    mma_tf32(accG[fm][fn], af[fm], bfg[fn]);
                }
        }
    }

    // Epilogue: h = gelu(up) * (gate + 1)
#pragma unroll
    for (int fm = 0; fm < 2; fm++) {
        int r0 = wm * 32 + fm * 16 + grp;
#pragma unroll
        for (int half = 0; half < 2; half++) {
            int gm = m0 + r0 + half * 8;
            if (gm < cnt) {
                float* hrow = g_h + (size_t)(off + gm) * N_INT + n0;
#pragma unroll
                for (int fn = 0; fn < 4; fn++) {
                    int c = wn * 32 + fn * 8 + qid * 2;
                    float u0 = accU[fm][fn][half * 2 + 0];
                    float u1 = accU[fm][fn][half * 2 + 1];
                    float g0 = accG[fm][fn][half * 2 + 0];
                    float g1 = accG[fm][fn][half * 2 + 1];
                    float2 r;
                    r.x = gelu_exact(u0) * (g0 + 1.0f);
                    r.y = gelu_exact(u1) * (g1 + 1.0f);
                    *(float2*)(hrow + c) = r;
                }
            }
        }
    }
}

// ---------------------------------------------------------------------------
// GEMM 2: out_slot = w * (h @ Wd), tiles 128x128x32, 256 thr, 3-stage
//   smem per stage: A 128x36, Bd 32x136 (floats)
// ---------------------------------------------------------------------------
#define G2_BM 128
#define G2_BN 128
#define G2_BK 32
#define G2_AS 36
#define G2_BS 136
#define G2_A_SZ  (G2_BM * G2_AS)          // 4608
#define G2_B_SZ  (G2_BK * G2_BS)          // 4352
#define G2_STAGE (G2_A_SZ + G2_B_SZ)

__global__ void __launch_bounds__(256)
gemm2_kernel(const float* __restrict__ w_down) {
    int e   = blockIdx.z;
    int cnt = g_counts[e];
    int m0  = blockIdx.y * G2_BM;
    if (m0 >= cnt) return;
    int n0  = blockIdx.x * G2_BN;
    int off = g_offsets[e];

    const float* Wd = w_down + (size_t)e * N_INT * D_HID;

    float* As = smem_dyn;                    // [STAGES][128][36]
    float* Bd = smem_dyn + STAGES * G2_A_SZ; // [STAGES][32][136]

    int tid  = threadIdx.x;
    int warp = tid >> 5, lane = tid & 31;
    int grp  = lane >> 2, qid = lane & 3;
    int wm   = warp >> 2, wn  = warp & 3;    // 2x4 warp grid, 64x32 tiles

    int arow = tid >> 3;
    int acol = (tid & 7) * 4;
    const float* aptr[4];
#pragma unroll
    for (int i = 0; i < 4; i++) {
        int gm   = m0 + arow + 32 * i;
        int slot = (gm < cnt) ? (off + gm) : off;
        aptr[i]  = g_h + (size_t)slot * N_INT + acol;
    }
    int brow = tid >> 5;          // 0..7 (8 rows/pass, 4 passes)
    int bcol = (tid & 31) * 4;    // 32 * 16B = 512B = 128 floats

    float acc[4][4][4];
#pragma unroll
    for (int a = 0; a < 4; a++)
#pragma unroll
        for (int b = 0; b < 4; b++)
#pragma unroll
            for (int c = 0; c < 4; c++) acc[a][b][c] = 0.f;

    const int KT = N_INT / G2_BK;   // 32

    auto load_stage = [&](int s, int k0) {
        float* a = As + s * G2_A_SZ;
#pragma unroll
        for (int i = 0; i < 4; i++)
            cp_async16(a + (arow + 32 * i) * G2_AS + acol, aptr[i] + k0);
        float* b = Bd + s * G2_B_SZ;
#pragma unroll
        for (int i = 0; i < 4; i++) {
            int kr = brow + 8 * i;
            cp_async16(b + kr * G2_BS + bcol, Wd + (size_t)(k0 + kr) * D_HID + n0 + bcol);
        }
        cp_commit();
    };

#pragma unroll
    for (int s = 0; s < STAGES - 1; s++) load_stage(s, s * G2_BK);

    for (int kt = 0; kt < KT; kt++) {
        cp_wait<STAGES - 2>();
        __syncthreads();

        int nkt = kt + STAGES - 1;
        if (nkt < KT) load_stage(nkt % STAGES, nkt * G2_BK);
        else          cp_commit();

        int s = kt % STAGES;
        const float* a = As + s * G2_A_SZ;
        const float* b = Bd + s * G2_B_SZ;

#pragma unroll
        for (int ks = 0; ks < 4; ks++) {
            int kk = ks * 8;
            uint32_t af[4][4];
#pragma unroll
            for (int fm = 0; fm < 4; fm++) {
                int rb = wm * 64 + fm * 16;
                af[fm][0] = f2tf32(a[(rb + grp)     * G2_AS + kk + qid]);
                af[fm][1] = f2tf32(a[(rb + grp + 8) * G2_AS + kk + qid]);
                af[fm][2] = f2tf32(a[(rb + grp)     * G2_AS + kk + qid + 4]);
                af[fm][3] = f2tf32(a[(rb + grp + 8) * G2_AS + kk + qid + 4]);
            }
            uint32_t bf[4][2];
#pragma unroll
            for (int fn = 0; fn < 4; fn++) {
                int cb = wn * 32 + fn * 8 + grp;
                bf[fn][0] = f2tf32(b[(kk + qid)     * G2_BS + cb]);
                bf[fn][1] = f2tf32(b[(kk + qid + 4) * G2_BS + cb]);
            }
#pragma unroll
            for (int fm = 0; fm < 4; fm++)
#pragma unroll
                for (int fn = 0; fn < 4; fn++)
                    mma_tf32(acc[fm][fn], af[fm], bf[fn]);
        }
    }

    // Epilogue
#pragma unroll
    for (int fm = 0; fm < 4; fm++) {
        int r0 = wm * 64 + fm * 16 + grp;
#pragma unroll
        for (int half = 0; half < 2; half++) {
            int gm = m0 + r0 + half * 8;
            if (gm < cnt) {
                int slot = off + gm;
                int dest = g_slot_tok2[slot];
                float wv = g_slot_w[slot];
                float* orow = g_oslots + (size_t)dest * D_HID + n0;
#pragma unroll
                for (int fn = 0; fn < 4; fn++) {
                    int c = wn * 32 + fn * 8 + qid * 2;
                    float2 r;
                    r.x = wv * acc[fm][fn][half * 2 + 0];
                    r.y = wv * acc[fm][fn][half * 2 + 1];
                    *(float2*)(orow + c) = r;
                }
            }
        }
    }
}

// ---------------------------------------------------------------------------
// 7) combine
// ---------------------------------------------------------------------------
__global__ void combine_kernel(float* __restrict__ out) {
    int i = blockIdx.x * blockDim.x + threadIdx.x;
    int t = i >> 9;
    int c = (i & 511) << 2;
    const float4 a = *(const float4*)(g_oslots + ((size_t)(2 * t)) * D_HID + c);
    const float4 b = *(const float4*)(g_oslots + ((size_t)(2 * t) + 1) * D_HID + c);
    float4 r;
    r.x = a.x + b.x; r.y = a.y + b.y; r.z = a.z + b.z; r.w = a.w + b.w;
    *(float4*)(out + (size_t)t * D_HID + c) = r;
}

// ---------------------------------------------------------------------------
// Launch
// ---------------------------------------------------------------------------
extern "C" void kernel_launch(void* const* d_in, const int* in_sizes, int n_in,
                              void* d_out, int out_size) {
    const float* x  = (const float*)d_in[0];
    const float* gw = (const float*)d_in[1];
    const float* gb = (const float*)d_in[2];
    const float* wu = (const float*)d_in[3];
    const float* wg = (const float*)d_in[4];
    const float* wd = (const float*)d_in[5];

    float* out    = (float*)d_out;
    float* logits = out + (out_size - T_TOK * N_EXP);

    static int attr_done = 0;
    // (idempotent; called every launch — deterministic)
    cudaFuncSetAttribute(gemm1_kernel, cudaFuncAttributeMaxDynamicSharedMemorySize,
                         STAGES * G1_STAGE * (int)sizeof(float));
    cudaFuncSetAttribute(gemm2_kernel, cudaFuncAttributeMaxDynamicSharedMemorySize,
                         STAGES * G2_STAGE * (int)sizeof(float));
    (void)attr_done;

    init_kernel<<<1, 32>>>();
    router_kernel<<<T_TOK, 256>>>(x, gw, gb, logits);
    offsets_kernel<<<1, 32>>>();
    scatter_kernel<<<(N_SLOT + 255) / 256, 256>>>();

    dim3 g1(N_INT / G1_BN, N_SLOT / G1_BM, N_EXP);   // (16, 32, 8)
    gemm1_kernel<<<g1, 256, STAGES * G1_STAGE * sizeof(float)>>>(x, wu, wg);

    dim3 g2(D_HID / G2_BN, N_SLOT / G2_BM, N_EXP);   // (16, 32, 8)
    gemm2_kernel<<<g2, 256, STAGES * G2_STAGE * sizeof(float)>>>(wd);

    combine_kernel<<<(T_TOK * D_HID / 4) / 256, 256>>>(out);
}